// round 1
// baseline (speedup 1.0000x reference)
#include <cuda_runtime.h>
#include <math.h>

#define D_MODEL 2048
#define NH 16
#define HD 128
#define SEQ 2048
#define BATCH 4
#define ROWS (BATCH * SEQ)       // 8192
#define D_FF 8192
#define QKV_N (3 * D_MODEL)      // 6144

// -------- scratch (static device globals; no cudaMalloc allowed) --------
__device__ float g_h[(size_t)ROWS * D_MODEL];      // LN output (reused)
__device__ float g_qkv[(size_t)ROWS * QKV_N];      // fused QKV
__device__ float g_attn[(size_t)ROWS * D_MODEL];   // attention output
__device__ float g_mlp[(size_t)ROWS * D_FF];       // MLP hidden

// ============================ LayerNorm ============================
// one block per row, 256 threads, D=2048 -> 2 float4 per thread
__global__ void __launch_bounds__(256) ln_kernel(
    const float* __restrict__ x, const float* __restrict__ g,
    const float* __restrict__ b, float* __restrict__ out)
{
    __shared__ float red[2][8];
    int row = blockIdx.x, tid = threadIdx.x;
    const float4* xr = (const float4*)(x + (size_t)row * D_MODEL);
    float4 v0 = xr[tid];
    float4 v1 = xr[tid + 256];
    float s  = v0.x + v0.y + v0.z + v0.w + v1.x + v1.y + v1.z + v1.w;
    float s2 = v0.x*v0.x + v0.y*v0.y + v0.z*v0.z + v0.w*v0.w
             + v1.x*v1.x + v1.y*v1.y + v1.z*v1.z + v1.w*v1.w;
    #pragma unroll
    for (int o = 16; o; o >>= 1) {
        s  += __shfl_xor_sync(0xffffffffu, s,  o);
        s2 += __shfl_xor_sync(0xffffffffu, s2, o);
    }
    if ((tid & 31) == 0) { red[0][tid >> 5] = s; red[1][tid >> 5] = s2; }
    __syncthreads();
    if (tid < 32) {
        float a = (tid < 8) ? red[0][tid] : 0.f;
        float c = (tid < 8) ? red[1][tid] : 0.f;
        #pragma unroll
        for (int o = 4; o; o >>= 1) {
            a += __shfl_xor_sync(0xffffffffu, a, o);
            c += __shfl_xor_sync(0xffffffffu, c, o);
        }
        if (tid == 0) { red[0][0] = a; red[1][0] = c; }
    }
    __syncthreads();
    float mean = red[0][0] * (1.f / D_MODEL);
    float var  = red[1][0] * (1.f / D_MODEL) - mean * mean;
    float rstd = rsqrtf(var + 1e-5f);

    const float4* gr = (const float4*)g;
    const float4* br = (const float4*)b;
    float4* orow = (float4*)(out + (size_t)row * D_MODEL);
    #pragma unroll
    for (int p = 0; p < 2; p++) {
        float4 v = p ? v1 : v0;
        float4 gw = gr[tid + p * 256];
        float4 bw = br[tid + p * 256];
        float4 o;
        o.x = (v.x - mean) * rstd * gw.x + bw.x;
        o.y = (v.y - mean) * rstd * gw.y + bw.y;
        o.z = (v.z - mean) * rstd * gw.z + bw.z;
        o.w = (v.w - mean) * rstd * gw.w + bw.w;
        orow[tid + p * 256] = o;
    }
}

// ============================ GEMM ============================
// C[M,N] = A[M,K] @ B[N,K]^T + bias[N]  (+ epilogue)
// EPI: 0 = bias, 1 = bias + residual add, 2 = bias + exact GELU
#define BM 128
#define BN 128
#define BK 8

__device__ __forceinline__ float gelu_exact(float v) {
    return 0.5f * v * (1.0f + erff(v * 0.70710678118654752f));
}

template <int EPI>
__global__ void __launch_bounds__(256) gemm_kernel(
    const float* __restrict__ A, const float* __restrict__ B,
    const float* __restrict__ bias, const float* __restrict__ res,
    float* __restrict__ C, int M, int N, int K)
{
    __shared__ float As[BK][BM + 4];
    __shared__ float Bs[BK][BN + 4];
    int tid = threadIdx.x;
    int bm = blockIdx.y, bn = blockIdx.x;
    int lrow = tid >> 1;            // 0..127
    int lk   = (tid & 1) * 4;       // 0 or 4
    const float* Aptr = A + (size_t)(bm * BM + lrow) * K + lk;
    const float* Bptr = B + (size_t)(bn * BN + lrow) * K + lk;
    int ty = tid >> 4, tx = tid & 15;
    int row0 = ty * 8, col0 = tx * 8;

    float acc[8][8];
    #pragma unroll
    for (int i = 0; i < 8; i++)
        #pragma unroll
        for (int j = 0; j < 8; j++) acc[i][j] = 0.f;

    float4 a4 = *(const float4*)Aptr;
    float4 b4 = *(const float4*)Bptr;
    int ktiles = K / BK;

    for (int kt = 0; kt < ktiles; ++kt) {
        __syncthreads();
        As[lk + 0][lrow] = a4.x; As[lk + 1][lrow] = a4.y;
        As[lk + 2][lrow] = a4.z; As[lk + 3][lrow] = a4.w;
        Bs[lk + 0][lrow] = b4.x; Bs[lk + 1][lrow] = b4.y;
        Bs[lk + 2][lrow] = b4.z; Bs[lk + 3][lrow] = b4.w;
        __syncthreads();
        if (kt + 1 < ktiles) {                  // prefetch next tile
            a4 = *(const float4*)(Aptr + (kt + 1) * BK);
            b4 = *(const float4*)(Bptr + (kt + 1) * BK);
        }
        #pragma unroll
        for (int k = 0; k < BK; k++) {
            float ar[8], br[8];
            *(float4*)&ar[0] = *(const float4*)&As[k][row0];
            *(float4*)&ar[4] = *(const float4*)&As[k][row0 + 4];
            *(float4*)&br[0] = *(const float4*)&Bs[k][col0];
            *(float4*)&br[4] = *(const float4*)&Bs[k][col0 + 4];
            #pragma unroll
            for (int i = 0; i < 8; i++)
                #pragma unroll
                for (int j = 0; j < 8; j++)
                    acc[i][j] = fmaf(ar[i], br[j], acc[i][j]);
        }
    }

    int grow0 = bm * BM + row0;
    int gcol0 = bn * BN + col0;
    #pragma unroll
    for (int i = 0; i < 8; i++) {
        size_t off = (size_t)(grow0 + i) * N + gcol0;
        #pragma unroll
        for (int j4 = 0; j4 < 2; j4++) {
            float4 v;
            v.x = acc[i][j4 * 4 + 0] + bias[gcol0 + j4 * 4 + 0];
            v.y = acc[i][j4 * 4 + 1] + bias[gcol0 + j4 * 4 + 1];
            v.z = acc[i][j4 * 4 + 2] + bias[gcol0 + j4 * 4 + 2];
            v.w = acc[i][j4 * 4 + 3] + bias[gcol0 + j4 * 4 + 3];
            if (EPI == 1) {
                float4 r = *(const float4*)(res + off + j4 * 4);
                v.x += r.x; v.y += r.y; v.z += r.z; v.w += r.w;
            }
            if (EPI == 2) {
                v.x = gelu_exact(v.x); v.y = gelu_exact(v.y);
                v.z = gelu_exact(v.z); v.w = gelu_exact(v.w);
            }
            *(float4*)(C + off + j4 * 4) = v;
        }
    }
}

// ============================ Flash attention (fp32) ============================
// Grid: (SEQ/64, NH, BATCH), 256 threads.
// smem: Qs[64][129], Ks[64][129], Vs[64][129], Ps[64][65]  -> 115712 B dynamic
#define ATT_SMEM ((3 * 64 * 129 + 64 * 65) * 4)

__global__ void __launch_bounds__(256) attn_kernel(
    const float* __restrict__ qkv, const float* __restrict__ slopes,
    float* __restrict__ out)
{
    extern __shared__ float sm[];
    float* Qs = sm;                    // 64*129
    float* Ks = Qs + 64 * 129;
    float* Vs = Ks + 64 * 129;
    float* Ps = Vs + 64 * 129;         // 64*65

    int qi = blockIdx.x, h = blockIdx.y, b = blockIdx.z;
    int tid = threadIdx.x, tx = tid & 15, ty = tid >> 4;
    int q0 = qi * 64;
    const float scale = 0.08838834764831845f;  // 1/sqrt(128)
    float slope = slopes[h];

    const float* qbase = qkv + (size_t)(b * SEQ) * QKV_N + h * HD;
    const float* kbase = qbase + D_MODEL;
    const float* vbase = qbase + 2 * D_MODEL;

    // load Q tile, pre-scaled
    for (int i = tid; i < 64 * 32; i += 256) {
        int r = i >> 5, f = (i & 31) * 4;
        float4 v = *(const float4*)(qbase + (size_t)(q0 + r) * QKV_N + f);
        float* d = &Qs[r * 129 + f];
        d[0] = v.x * scale; d[1] = v.y * scale; d[2] = v.z * scale; d[3] = v.w * scale;
    }

    float m[4], l[4], acc[4][8];
    #pragma unroll
    for (int i = 0; i < 4; i++) {
        m[i] = -INFINITY; l[i] = 0.f;
        #pragma unroll
        for (int j = 0; j < 8; j++) acc[i][j] = 0.f;
    }

    for (int jt = 0; jt <= qi; ++jt) {
        int j0 = jt * 64;
        // load K, V tiles
        for (int i = tid; i < 64 * 32; i += 256) {
            int r = i >> 5, f = (i & 31) * 4;
            float4 kv = *(const float4*)(kbase + (size_t)(j0 + r) * QKV_N + f);
            float* kd = &Ks[r * 129 + f];
            kd[0] = kv.x; kd[1] = kv.y; kd[2] = kv.z; kd[3] = kv.w;
            float4 vv = *(const float4*)(vbase + (size_t)(j0 + r) * QKV_N + f);
            float* vd = &Vs[r * 129 + f];
            vd[0] = vv.x; vd[1] = vv.y; vd[2] = vv.z; vd[3] = vv.w;
        }
        __syncthreads();   // KV (and Q on first iter) visible

        // scores s[4][4] = Q K^T (Q pre-scaled)
        float s[4][4];
        #pragma unroll
        for (int i = 0; i < 4; i++)
            #pragma unroll
            for (int j = 0; j < 4; j++) s[i][j] = 0.f;
        const float* qrow = &Qs[(ty * 4) * 129];
        const float* krow = &Ks[(tx * 4) * 129];
        #pragma unroll 4
        for (int d = 0; d < HD; d++) {
            float qv[4], kv[4];
            #pragma unroll
            for (int i = 0; i < 4; i++) qv[i] = qrow[i * 129 + d];
            #pragma unroll
            for (int j = 0; j < 4; j++) kv[j] = krow[j * 129 + d];
            #pragma unroll
            for (int i = 0; i < 4; i++)
                #pragma unroll
                for (int j = 0; j < 4; j++)
                    s[i][j] = fmaf(qv[i], kv[j], s[i][j]);
        }

        // ALiBi + causal mask + online softmax
        #pragma unroll
        for (int i = 0; i < 4; i++) {
            int grow = q0 + ty * 4 + i;
            float tm = -INFINITY;
            #pragma unroll
            for (int j = 0; j < 4; j++) {
                int gcol = j0 + tx * 4 + j;
                if (gcol > grow) s[i][j] = -INFINITY;
                else s[i][j] += slope * (float)(gcol - grow);
                tm = fmaxf(tm, s[i][j]);
            }
            #pragma unroll
            for (int o = 1; o < 16; o <<= 1)
                tm = fmaxf(tm, __shfl_xor_sync(0xffffffffu, tm, o));
            float mn = fmaxf(m[i], tm);
            float ts = 0.f;
            #pragma unroll
            for (int j = 0; j < 4; j++) {
                float p = __expf(s[i][j] - mn);
                s[i][j] = p;
                ts += p;
            }
            #pragma unroll
            for (int o = 1; o < 16; o <<= 1)
                ts += __shfl_xor_sync(0xffffffffu, ts, o);
            float alpha = __expf(m[i] - mn);
            m[i] = mn;
            l[i] = l[i] * alpha + ts;
            #pragma unroll
            for (int jj = 0; jj < 8; jj++) acc[i][jj] *= alpha;
        }

        // stage P
        #pragma unroll
        for (int i = 0; i < 4; i++)
            #pragma unroll
            for (int j = 0; j < 4; j++)
                Ps[(ty * 4 + i) * 65 + tx * 4 + j] = s[i][j];
        __syncthreads();

        // O += P @ V   (thread owns cols d = tx + 16*jj -> conflict-free V reads)
        #pragma unroll 2
        for (int c = 0; c < 64; c++) {
            float pv[4];
            #pragma unroll
            for (int i = 0; i < 4; i++) pv[i] = Ps[(ty * 4 + i) * 65 + c];
            float vv[8];
            #pragma unroll
            for (int jj = 0; jj < 8; jj++) vv[jj] = Vs[c * 129 + tx + 16 * jj];
            #pragma unroll
            for (int i = 0; i < 4; i++)
                #pragma unroll
                for (int jj = 0; jj < 8; jj++)
                    acc[i][jj] = fmaf(pv[i], vv[jj], acc[i][jj]);
        }
        __syncthreads();   // protect K/V/P before next tile
    }

    // write output: [B*S, D] with this head's 128-col slice
    float* obase = out + (size_t)(b * SEQ + q0) * D_MODEL + h * HD;
    #pragma unroll
    for (int i = 0; i < 4; i++) {
        float inv = 1.f / l[i];
        #pragma unroll
        for (int jj = 0; jj < 8; jj++)
            obase[(size_t)(ty * 4 + i) * D_MODEL + tx + 16 * jj] = acc[i][jj] * inv;
    }
}

// ============================ launch ============================
extern "C" void kernel_launch(void* const* d_in, const int* in_sizes, int n_in,
                              void* d_out, int out_size)
{
    const float* x      = (const float*)d_in[0];
    const float* ln1_w  = (const float*)d_in[1];
    const float* ln1_b  = (const float*)d_in[2];
    const float* Wqkv   = (const float*)d_in[3];
    const float* bqkv   = (const float*)d_in[4];
    const float* Wo     = (const float*)d_in[5];
    const float* bo     = (const float*)d_in[6];
    const float* ln2_w  = (const float*)d_in[7];
    const float* ln2_b  = (const float*)d_in[8];
    const float* W1     = (const float*)d_in[9];
    const float* b1     = (const float*)d_in[10];
    const float* W2     = (const float*)d_in[11];
    const float* b2     = (const float*)d_in[12];
    const float* slopes = (const float*)d_in[13];
    float* out = (float*)d_out;

    float *h, *qkv, *attn, *mlp;
    cudaGetSymbolAddress((void**)&h,    g_h);
    cudaGetSymbolAddress((void**)&qkv,  g_qkv);
    cudaGetSymbolAddress((void**)&attn, g_attn);
    cudaGetSymbolAddress((void**)&mlp,  g_mlp);

    cudaFuncSetAttribute(attn_kernel,
                         cudaFuncAttributeMaxDynamicSharedMemorySize, ATT_SMEM);

    // 1. LN1
    ln_kernel<<<ROWS, 256>>>(x, ln1_w, ln1_b, h);
    // 2. QKV GEMM
    gemm_kernel<0><<<dim3(QKV_N / BN, ROWS / BM), 256>>>(
        h, Wqkv, bqkv, nullptr, qkv, ROWS, QKV_N, D_MODEL);
    // 3. Flash attention with ALiBi
    attn_kernel<<<dim3(SEQ / 64, NH, BATCH), 256, ATT_SMEM>>>(qkv, slopes, attn);
    // 4. O projection + residual (x)  -> d_out holds x1
    gemm_kernel<1><<<dim3(D_MODEL / BN, ROWS / BM), 256>>>(
        attn, Wo, bo, x, out, ROWS, D_MODEL, D_MODEL);
    // 5. LN2
    ln_kernel<<<ROWS, 256>>>(out, ln2_w, ln2_b, h);
    // 6. MLP up + GELU
    gemm_kernel<2><<<dim3(D_FF / BN, ROWS / BM), 256>>>(
        h, W1, b1, nullptr, mlp, ROWS, D_FF, D_MODEL);
    // 7. MLP down + residual (x1 in d_out) -> d_out final
    gemm_kernel<1><<<dim3(D_MODEL / BN, ROWS / BM), 256>>>(
        mlp, W2, b2, out, out, ROWS, D_MODEL, D_FF);
}

// round 2
// speedup vs baseline: 3.6612x; 3.6612x over previous
#include <cuda_runtime.h>
#include <math.h>

#define D_MODEL 2048
#define NH 16
#define HD 128
#define SEQ 2048
#define BATCH 4
#define ROWS (BATCH * SEQ)       // 8192
#define D_FF 8192
#define QKV_N (3 * D_MODEL)      // 6144

// -------- scratch (static device globals; no cudaMalloc allowed) --------
__device__ float g_h[(size_t)ROWS * D_MODEL];      // LN output (reused)
__device__ float g_qkv[(size_t)ROWS * QKV_N];      // fused QKV
__device__ float g_attn[(size_t)ROWS * D_MODEL];   // attention output
__device__ float g_mlp[(size_t)ROWS * D_FF];       // MLP hidden

// ============================ LayerNorm ============================
__global__ void __launch_bounds__(256) ln_kernel(
    const float* __restrict__ x, const float* __restrict__ g,
    const float* __restrict__ b, float* __restrict__ out)
{
    __shared__ float red[2][8];
    int row = blockIdx.x, tid = threadIdx.x;
    const float4* xr = (const float4*)(x + (size_t)row * D_MODEL);
    float4 v0 = xr[tid];
    float4 v1 = xr[tid + 256];
    float s  = v0.x + v0.y + v0.z + v0.w + v1.x + v1.y + v1.z + v1.w;
    float s2 = v0.x*v0.x + v0.y*v0.y + v0.z*v0.z + v0.w*v0.w
             + v1.x*v1.x + v1.y*v1.y + v1.z*v1.z + v1.w*v1.w;
    #pragma unroll
    for (int o = 16; o; o >>= 1) {
        s  += __shfl_xor_sync(0xffffffffu, s,  o);
        s2 += __shfl_xor_sync(0xffffffffu, s2, o);
    }
    if ((tid & 31) == 0) { red[0][tid >> 5] = s; red[1][tid >> 5] = s2; }
    __syncthreads();
    if (tid < 32) {
        float a = (tid < 8) ? red[0][tid] : 0.f;
        float c = (tid < 8) ? red[1][tid] : 0.f;
        #pragma unroll
        for (int o = 4; o; o >>= 1) {
            a += __shfl_xor_sync(0xffffffffu, a, o);
            c += __shfl_xor_sync(0xffffffffu, c, o);
        }
        if (tid == 0) { red[0][0] = a; red[1][0] = c; }
    }
    __syncthreads();
    float mean = red[0][0] * (1.f / D_MODEL);
    float var  = red[1][0] * (1.f / D_MODEL) - mean * mean;
    float rstd = rsqrtf(var + 1e-5f);

    const float4* gr = (const float4*)g;
    const float4* br = (const float4*)b;
    float4* orow = (float4*)(out + (size_t)row * D_MODEL);
    #pragma unroll
    for (int p = 0; p < 2; p++) {
        float4 v = p ? v1 : v0;
        float4 gw = gr[tid + p * 256];
        float4 bw = br[tid + p * 256];
        float4 o;
        o.x = (v.x - mean) * rstd * gw.x + bw.x;
        o.y = (v.y - mean) * rstd * gw.y + bw.y;
        o.z = (v.z - mean) * rstd * gw.z + bw.z;
        o.w = (v.w - mean) * rstd * gw.w + bw.w;
        orow[tid + p * 256] = o;
    }
}

// ============================ tf32 tensor-core GEMM ============================
// C[M,N] = A[M,K] @ B[N,K]^T + bias[N]  (+ epilogue)
// EPI: 0 = bias, 1 = bias + residual add, 2 = bias + exact GELU
// Tiles: CTA 128x128xBK32, 8 warps as 4(m) x 2(n), warp tile 32x64.
// smem layout per tile: [128 rows][32 floats], with k permuted kk=(k%4)*8+k/4
// and float4-group XOR swizzle: phys_f4 = f4 ^ (row & 7). Makes all fragment
// reads conflict-free LDS.128.

#define GBM 128
#define GBN 128
#define GBK 32
#define GEMM_SMEM (4 * 128 * 32 * 4)   // 2 bufs x (A+B) = 65536 B

__device__ __forceinline__ float gelu_exact(float v) {
    return 0.5f * v * (1.0f + erff(v * 0.70710678118654752f));
}

__device__ __forceinline__ float tf32r(float f) {
    unsigned u;
    asm("cvt.rna.tf32.f32 %0, %1;" : "=r"(u) : "f"(f));
    return __uint_as_float(u);
}

__device__ __forceinline__ void mma_tf32(float* c,
    float a0, float a1, float a2, float a3, float b0, float b1)
{
    asm volatile(
        "mma.sync.aligned.m16n8k8.row.col.f32.tf32.tf32.f32 "
        "{%0,%1,%2,%3}, {%4,%5,%6,%7}, {%8,%9}, {%0,%1,%2,%3};"
        : "+f"(c[0]), "+f"(c[1]), "+f"(c[2]), "+f"(c[3])
        : "r"(__float_as_uint(a0)), "r"(__float_as_uint(a1)),
          "r"(__float_as_uint(a2)), "r"(__float_as_uint(a3)),
          "r"(__float_as_uint(b0)), "r"(__float_as_uint(b1)));
}

struct Frag8 { float v[8]; };

// scatter one staged (thread-owned) set of 4 float4 into permuted+swizzled smem
__device__ __forceinline__ void stage_tile(const float4* st, float* buf, int tid)
{
    #pragma unroll
    for (int p = 0; p < 4; p++) {
        int idx = tid + 256 * p;
        int row = idx >> 3, c4 = idx & 7;      // c4 = k/4
        const float* e = (const float*)&st[p];
        #pragma unroll
        for (int ei = 0; ei < 4; ei++) {       // k = 4*c4 + ei -> kk = ei*8 + c4
            int f4l = 2 * ei + (c4 >> 2);
            int word = row * 32 + (((f4l ^ (row & 7))) << 2) + (c4 & 3);
            buf[word] = tf32r(e[ei]);
        }
    }
}

template <int EPI>
__global__ void __launch_bounds__(256, 1) gemm_kernel(
    const float* __restrict__ A, const float* __restrict__ B,
    const float* __restrict__ bias, const float* __restrict__ res,
    float* __restrict__ C, int M, int N, int K)
{
    extern __shared__ float sm[];
    // layout: Abuf0, Abuf1, Bbuf0, Bbuf1 each 4096 floats
    int tid = threadIdx.x;
    int bm = blockIdx.y, bn = blockIdx.x;
    int warp = tid >> 5, lane = tid & 31;
    int wm = warp >> 1, wn = warp & 1;
    int g = lane >> 2, c = lane & 3;

    // global staging addresses: thread p-th float4: idx = tid + 256p
    // row = idx>>3, c4 = idx&7 -> col = c4*4
    const float* Ag[4]; const float* Bg[4];
    #pragma unroll
    for (int p = 0; p < 4; p++) {
        int idx = tid + 256 * p;
        int row = idx >> 3, c4 = idx & 7;
        Ag[p] = A + (size_t)(bm * GBM + row) * K + c4 * 4;
        Bg[p] = B + (size_t)(bn * GBN + row) * K + c4 * 4;
    }

    float acc[2][8][4];
    #pragma unroll
    for (int mt = 0; mt < 2; mt++)
        #pragma unroll
        for (int nt = 0; nt < 8; nt++)
            #pragma unroll
            for (int q = 0; q < 4; q++) acc[mt][nt][q] = 0.f;

    int kt = K / GBK;

    // prologue: tile 0
    float4 stA[4], stB[4];
    #pragma unroll
    for (int p = 0; p < 4; p++) { stA[p] = *(const float4*)Ag[p];
                                  stB[p] = *(const float4*)Bg[p]; }
    stage_tile(stA, sm, tid);
    stage_tile(stB, sm + 8192, tid);
    __syncthreads();

    for (int kb = 0; kb < kt; ++kb) {
        int cur = kb & 1;
        if (kb + 1 < kt) {
            #pragma unroll
            for (int p = 0; p < 4; p++) {
                stA[p] = *(const float4*)(Ag[p] + (kb + 1) * GBK);
                stB[p] = *(const float4*)(Bg[p] + (kb + 1) * GBK);
            }
        }
        const float* Abuf = sm + cur * 4096;
        const float* Bbuf = sm + 8192 + cur * 4096;

        // load fragments (all conflict-free LDS.128)
        Frag8 fa[2][2];
        #pragma unroll
        for (int mt = 0; mt < 2; mt++)
            #pragma unroll
            for (int rr = 0; rr < 2; rr++) {
                int r = wm * 32 + mt * 16 + rr * 8 + g;
                const float* base = Abuf + r * 32;
                #pragma unroll
                for (int u = 0; u < 2; u++) {
                    int f4p = (2 * c + u) ^ (r & 7);
                    *(float4*)&fa[mt][rr].v[4 * u] = *(const float4*)(base + f4p * 4);
                }
            }
        Frag8 fb[8];
        #pragma unroll
        for (int nt = 0; nt < 8; nt++) {
            int r = wn * 64 + nt * 8 + g;
            const float* base = Bbuf + r * 32;
            #pragma unroll
            for (int u = 0; u < 2; u++) {
                int f4p = (2 * c + u) ^ (r & 7);
                *(float4*)&fb[nt].v[4 * u] = *(const float4*)(base + f4p * 4);
            }
        }

        #pragma unroll
        for (int s = 0; s < 4; s++)
            #pragma unroll
            for (int mt = 0; mt < 2; mt++)
                #pragma unroll
                for (int nt = 0; nt < 8; nt++)
                    mma_tf32(acc[mt][nt],
                        fa[mt][0].v[2*s], fa[mt][1].v[2*s],
                        fa[mt][0].v[2*s+1], fa[mt][1].v[2*s+1],
                        fb[nt].v[2*s], fb[nt].v[2*s+1]);

        if (kb + 1 < kt) {
            int nxt = 1 - cur;
            stage_tile(stA, sm + nxt * 4096, tid);
            stage_tile(stB, sm + 8192 + nxt * 4096, tid);
        }
        __syncthreads();
    }

    // epilogue: c0,c1 -> (row g, cols 2c,2c+1); c2,c3 -> (row g+8, same cols)
    int row0g = bm * GBM + wm * 32;
    int col0g = bn * GBN + wn * 64;
    #pragma unroll
    for (int mt = 0; mt < 2; mt++)
        #pragma unroll
        for (int nt = 0; nt < 8; nt++)
            #pragma unroll
            for (int h2 = 0; h2 < 2; h2++) {
                int row = row0g + mt * 16 + h2 * 8 + g;
                int col = col0g + nt * 8 + 2 * c;
                float2 v;
                v.x = acc[mt][nt][2 * h2 + 0] + bias[col];
                v.y = acc[mt][nt][2 * h2 + 1] + bias[col + 1];
                size_t off = (size_t)row * N + col;
                if (EPI == 1) {
                    float2 r = *(const float2*)(res + off);
                    v.x += r.x; v.y += r.y;
                }
                if (EPI == 2) {
                    v.x = gelu_exact(v.x); v.y = gelu_exact(v.y);
                }
                *(float2*)(C + off) = v;
            }
}

// ============================ Flash attention (fp32) ============================
#define ATT_SMEM ((3 * 64 * 129 + 64 * 65) * 4)

__global__ void __launch_bounds__(256) attn_kernel(
    const float* __restrict__ qkv, const float* __restrict__ slopes,
    float* __restrict__ out)
{
    extern __shared__ float sm[];
    float* Qs = sm;                    // 64*129
    float* Ks = Qs + 64 * 129;
    float* Vs = Ks + 64 * 129;
    float* Ps = Vs + 64 * 129;         // 64*65

    int qi = blockIdx.x, h = blockIdx.y, b = blockIdx.z;
    int tid = threadIdx.x, tx = tid & 15, ty = tid >> 4;
    int q0 = qi * 64;
    const float scale = 0.08838834764831845f;  // 1/sqrt(128)
    float slope = slopes[h];

    const float* qbase = qkv + (size_t)(b * SEQ) * QKV_N + h * HD;
    const float* kbase = qbase + D_MODEL;
    const float* vbase = qbase + 2 * D_MODEL;

    for (int i = tid; i < 64 * 32; i += 256) {
        int r = i >> 5, f = (i & 31) * 4;
        float4 v = *(const float4*)(qbase + (size_t)(q0 + r) * QKV_N + f);
        float* d = &Qs[r * 129 + f];
        d[0] = v.x * scale; d[1] = v.y * scale; d[2] = v.z * scale; d[3] = v.w * scale;
    }

    float m[4], l[4], acc[4][8];
    #pragma unroll
    for (int i = 0; i < 4; i++) {
        m[i] = -INFINITY; l[i] = 0.f;
        #pragma unroll
        for (int j = 0; j < 8; j++) acc[i][j] = 0.f;
    }

    for (int jt = 0; jt <= qi; ++jt) {
        int j0 = jt * 64;
        for (int i = tid; i < 64 * 32; i += 256) {
            int r = i >> 5, f = (i & 31) * 4;
            float4 kv = *(const float4*)(kbase + (size_t)(j0 + r) * QKV_N + f);
            float* kd = &Ks[r * 129 + f];
            kd[0] = kv.x; kd[1] = kv.y; kd[2] = kv.z; kd[3] = kv.w;
            float4 vv = *(const float4*)(vbase + (size_t)(j0 + r) * QKV_N + f);
            float* vd = &Vs[r * 129 + f];
            vd[0] = vv.x; vd[1] = vv.y; vd[2] = vv.z; vd[3] = vv.w;
        }
        __syncthreads();

        float s[4][4];
        #pragma unroll
        for (int i = 0; i < 4; i++)
            #pragma unroll
            for (int j = 0; j < 4; j++) s[i][j] = 0.f;
        const float* qrow = &Qs[(ty * 4) * 129];
        const float* krow = &Ks[(tx * 4) * 129];
        #pragma unroll 4
        for (int d = 0; d < HD; d++) {
            float qv[4], kv[4];
            #pragma unroll
            for (int i = 0; i < 4; i++) qv[i] = qrow[i * 129 + d];
            #pragma unroll
            for (int j = 0; j < 4; j++) kv[j] = krow[j * 129 + d];
            #pragma unroll
            for (int i = 0; i < 4; i++)
                #pragma unroll
                for (int j = 0; j < 4; j++)
                    s[i][j] = fmaf(qv[i], kv[j], s[i][j]);
        }

        #pragma unroll
        for (int i = 0; i < 4; i++) {
            int grow = q0 + ty * 4 + i;
            float tm = -INFINITY;
            #pragma unroll
            for (int j = 0; j < 4; j++) {
                int gcol = j0 + tx * 4 + j;
                if (gcol > grow) s[i][j] = -INFINITY;
                else s[i][j] += slope * (float)(gcol - grow);
                tm = fmaxf(tm, s[i][j]);
            }
            #pragma unroll
            for (int o = 1; o < 16; o <<= 1)
                tm = fmaxf(tm, __shfl_xor_sync(0xffffffffu, tm, o));
            float mn = fmaxf(m[i], tm);
            float ts = 0.f;
            #pragma unroll
            for (int j = 0; j < 4; j++) {
                float p = __expf(s[i][j] - mn);
                s[i][j] = p;
                ts += p;
            }
            #pragma unroll
            for (int o = 1; o < 16; o <<= 1)
                ts += __shfl_xor_sync(0xffffffffu, ts, o);
            float alpha = __expf(m[i] - mn);
            m[i] = mn;
            l[i] = l[i] * alpha + ts;
            #pragma unroll
            for (int jj = 0; jj < 8; jj++) acc[i][jj] *= alpha;
        }

        #pragma unroll
        for (int i = 0; i < 4; i++)
            #pragma unroll
            for (int j = 0; j < 4; j++)
                Ps[(ty * 4 + i) * 65 + tx * 4 + j] = s[i][j];
        __syncthreads();

        #pragma unroll 2
        for (int cc = 0; cc < 64; cc++) {
            float pv[4];
            #pragma unroll
            for (int i = 0; i < 4; i++) pv[i] = Ps[(ty * 4 + i) * 65 + cc];
            float vv[8];
            #pragma unroll
            for (int jj = 0; jj < 8; jj++) vv[jj] = Vs[cc * 129 + tx + 16 * jj];
            #pragma unroll
            for (int i = 0; i < 4; i++)
                #pragma unroll
                for (int jj = 0; jj < 8; jj++)
                    acc[i][jj] = fmaf(pv[i], vv[jj], acc[i][jj]);
        }
        __syncthreads();
    }

    float* obase = out + (size_t)(b * SEQ + q0) * D_MODEL + h * HD;
    #pragma unroll
    for (int i = 0; i < 4; i++) {
        float inv = 1.f / l[i];
        #pragma unroll
        for (int jj = 0; jj < 8; jj++)
            obase[(size_t)(ty * 4 + i) * D_MODEL + tx + 16 * jj] = acc[i][jj] * inv;
    }
}

// ============================ launch ============================
extern "C" void kernel_launch(void* const* d_in, const int* in_sizes, int n_in,
                              void* d_out, int out_size)
{
    const float* x      = (const float*)d_in[0];
    const float* ln1_w  = (const float*)d_in[1];
    const float* ln1_b  = (const float*)d_in[2];
    const float* Wqkv   = (const float*)d_in[3];
    const float* bqkv   = (const float*)d_in[4];
    const float* Wo     = (const float*)d_in[5];
    const float* bo     = (const float*)d_in[6];
    const float* ln2_w  = (const float*)d_in[7];
    const float* ln2_b  = (const float*)d_in[8];
    const float* W1     = (const float*)d_in[9];
    const float* b1     = (const float*)d_in[10];
    const float* W2     = (const float*)d_in[11];
    const float* b2     = (const float*)d_in[12];
    const float* slopes = (const float*)d_in[13];
    float* out = (float*)d_out;

    float *h, *qkv, *attn, *mlp;
    cudaGetSymbolAddress((void**)&h,    g_h);
    cudaGetSymbolAddress((void**)&qkv,  g_qkv);
    cudaGetSymbolAddress((void**)&attn, g_attn);
    cudaGetSymbolAddress((void**)&mlp,  g_mlp);

    cudaFuncSetAttribute(attn_kernel,
                         cudaFuncAttributeMaxDynamicSharedMemorySize, ATT_SMEM);
    cudaFuncSetAttribute(gemm_kernel<0>,
                         cudaFuncAttributeMaxDynamicSharedMemorySize, GEMM_SMEM);
    cudaFuncSetAttribute(gemm_kernel<1>,
                         cudaFuncAttributeMaxDynamicSharedMemorySize, GEMM_SMEM);
    cudaFuncSetAttribute(gemm_kernel<2>,
                         cudaFuncAttributeMaxDynamicSharedMemorySize, GEMM_SMEM);

    // 1. LN1
    ln_kernel<<<ROWS, 256>>>(x, ln1_w, ln1_b, h);
    // 2. QKV GEMM
    gemm_kernel<0><<<dim3(QKV_N / GBN, ROWS / GBM), 256, GEMM_SMEM>>>(
        h, Wqkv, bqkv, nullptr, qkv, ROWS, QKV_N, D_MODEL);
    // 3. Flash attention with ALiBi
    attn_kernel<<<dim3(SEQ / 64, NH, BATCH), 256, ATT_SMEM>>>(qkv, slopes, attn);
    // 4. O projection + residual (x)  -> d_out holds x1
    gemm_kernel<1><<<dim3(D_MODEL / GBN, ROWS / GBM), 256, GEMM_SMEM>>>(
        attn, Wo, bo, x, out, ROWS, D_MODEL, D_MODEL);
    // 5. LN2
    ln_kernel<<<ROWS, 256>>>(out, ln2_w, ln2_b, h);
    // 6. MLP up + GELU
    gemm_kernel<2><<<dim3(D_FF / GBN, ROWS / GBM), 256, GEMM_SMEM>>>(
        h, W1, b1, nullptr, mlp, ROWS, D_FF, D_MODEL);
    // 7. MLP down + residual (x1 in d_out) -> d_out final
    gemm_kernel<1><<<dim3(D_MODEL / GBN, ROWS / GBM), 256, GEMM_SMEM>>>(
        mlp, W2, b2, out, out, ROWS, D_MODEL, D_FF);
}

// round 3
// speedup vs baseline: 4.3208x; 1.1802x over previous
#include <cuda_runtime.h>
#include <math.h>

#define D_MODEL 2048
#define NH 16
#define HD 128
#define SEQ 2048
#define BATCH 4
#define ROWS (BATCH * SEQ)       // 8192
#define D_FF 8192
#define QKV_N (3 * D_MODEL)      // 6144

// -------- scratch (static device globals; no cudaMalloc allowed) --------
__device__ float g_h[(size_t)ROWS * D_MODEL];      // LN output (reused)
__device__ float g_qkv[(size_t)ROWS * QKV_N];      // fused QKV
__device__ float g_attn[(size_t)ROWS * D_MODEL];   // attention output
__device__ float g_mlp[(size_t)ROWS * D_FF];       // MLP hidden

// ============================ common mma helpers ============================
__device__ __forceinline__ float tf32r(float f) {
    unsigned u;
    asm("cvt.rna.tf32.f32 %0, %1;" : "=r"(u) : "f"(f));
    return __uint_as_float(u);
}

// m16n8k8 tf32: a0=(g,c) a1=(g+8,c) a2=(g,c+4) a3=(g+8,c+4); b0=(k=c,n=g) b1=(k=c+4,n=g)
// c0=(g,2c) c1=(g,2c+1) c2=(g+8,2c) c3=(g+8,2c+1)
__device__ __forceinline__ void mma_tf32(float* c,
    float a0, float a1, float a2, float a3, float b0, float b1)
{
    asm volatile(
        "mma.sync.aligned.m16n8k8.row.col.f32.tf32.tf32.f32 "
        "{%0,%1,%2,%3}, {%4,%5,%6,%7}, {%8,%9}, {%0,%1,%2,%3};"
        : "+f"(c[0]), "+f"(c[1]), "+f"(c[2]), "+f"(c[3])
        : "r"(__float_as_uint(a0)), "r"(__float_as_uint(a1)),
          "r"(__float_as_uint(a2)), "r"(__float_as_uint(a3)),
          "r"(__float_as_uint(b0)), "r"(__float_as_uint(b1)));
}

// ============================ LayerNorm ============================
__global__ void __launch_bounds__(256) ln_kernel(
    const float* __restrict__ x, const float* __restrict__ g,
    const float* __restrict__ b, float* __restrict__ out)
{
    __shared__ float red[2][8];
    int row = blockIdx.x, tid = threadIdx.x;
    const float4* xr = (const float4*)(x + (size_t)row * D_MODEL);
    float4 v0 = xr[tid];
    float4 v1 = xr[tid + 256];
    float s  = v0.x + v0.y + v0.z + v0.w + v1.x + v1.y + v1.z + v1.w;
    float s2 = v0.x*v0.x + v0.y*v0.y + v0.z*v0.z + v0.w*v0.w
             + v1.x*v1.x + v1.y*v1.y + v1.z*v1.z + v1.w*v1.w;
    #pragma unroll
    for (int o = 16; o; o >>= 1) {
        s  += __shfl_xor_sync(0xffffffffu, s,  o);
        s2 += __shfl_xor_sync(0xffffffffu, s2, o);
    }
    if ((tid & 31) == 0) { red[0][tid >> 5] = s; red[1][tid >> 5] = s2; }
    __syncthreads();
    if (tid < 32) {
        float a = (tid < 8) ? red[0][tid] : 0.f;
        float c = (tid < 8) ? red[1][tid] : 0.f;
        #pragma unroll
        for (int o = 4; o; o >>= 1) {
            a += __shfl_xor_sync(0xffffffffu, a, o);
            c += __shfl_xor_sync(0xffffffffu, c, o);
        }
        if (tid == 0) { red[0][0] = a; red[1][0] = c; }
    }
    __syncthreads();
    float mean = red[0][0] * (1.f / D_MODEL);
    float var  = red[1][0] * (1.f / D_MODEL) - mean * mean;
    float rstd = rsqrtf(var + 1e-5f);

    const float4* gr = (const float4*)g;
    const float4* br = (const float4*)b;
    float4* orow = (float4*)(out + (size_t)row * D_MODEL);
    #pragma unroll
    for (int p = 0; p < 2; p++) {
        float4 v = p ? v1 : v0;
        float4 gw = gr[tid + p * 256];
        float4 bw = br[tid + p * 256];
        float4 o;
        o.x = (v.x - mean) * rstd * gw.x + bw.x;
        o.y = (v.y - mean) * rstd * gw.y + bw.y;
        o.z = (v.z - mean) * rstd * gw.z + bw.z;
        o.w = (v.w - mean) * rstd * gw.w + bw.w;
        orow[tid + p * 256] = o;
    }
}

// ============================ tf32 tensor-core GEMM ============================
#define GBM 128
#define GBN 128
#define GBK 32
#define GEMM_SMEM (4 * 128 * 32 * 4)   // 2 bufs x (A+B) = 65536 B

__device__ __forceinline__ float gelu_exact(float v) {
    return 0.5f * v * (1.0f + erff(v * 0.70710678118654752f));
}

struct Frag8 { float v[8]; };

__device__ __forceinline__ void stage_tile(const float4* st, float* buf, int tid)
{
    #pragma unroll
    for (int p = 0; p < 4; p++) {
        int idx = tid + 256 * p;
        int row = idx >> 3, c4 = idx & 7;      // c4 = k/4
        const float* e = (const float*)&st[p];
        #pragma unroll
        for (int ei = 0; ei < 4; ei++) {       // k = 4*c4 + ei -> kk = ei*8 + c4
            int f4l = 2 * ei + (c4 >> 2);
            int word = row * 32 + (((f4l ^ (row & 7))) << 2) + (c4 & 3);
            buf[word] = tf32r(e[ei]);
        }
    }
}

template <int EPI>
__global__ void __launch_bounds__(256, 1) gemm_kernel(
    const float* __restrict__ A, const float* __restrict__ B,
    const float* __restrict__ bias, const float* __restrict__ res,
    float* __restrict__ C, int M, int N, int K)
{
    extern __shared__ float sm[];
    int tid = threadIdx.x;
    int bm = blockIdx.y, bn = blockIdx.x;
    int warp = tid >> 5, lane = tid & 31;
    int wm = warp >> 1, wn = warp & 1;
    int g = lane >> 2, c = lane & 3;

    const float* Ag[4]; const float* Bg[4];
    #pragma unroll
    for (int p = 0; p < 4; p++) {
        int idx = tid + 256 * p;
        int row = idx >> 3, c4 = idx & 7;
        Ag[p] = A + (size_t)(bm * GBM + row) * K + c4 * 4;
        Bg[p] = B + (size_t)(bn * GBN + row) * K + c4 * 4;
    }

    float acc[2][8][4];
    #pragma unroll
    for (int mt = 0; mt < 2; mt++)
        #pragma unroll
        for (int nt = 0; nt < 8; nt++)
            #pragma unroll
            for (int q = 0; q < 4; q++) acc[mt][nt][q] = 0.f;

    int kt = K / GBK;

    float4 stA[4], stB[4];
    #pragma unroll
    for (int p = 0; p < 4; p++) { stA[p] = *(const float4*)Ag[p];
                                  stB[p] = *(const float4*)Bg[p]; }
    stage_tile(stA, sm, tid);
    stage_tile(stB, sm + 8192, tid);
    __syncthreads();

    for (int kb = 0; kb < kt; ++kb) {
        int cur = kb & 1;
        if (kb + 1 < kt) {
            #pragma unroll
            for (int p = 0; p < 4; p++) {
                stA[p] = *(const float4*)(Ag[p] + (kb + 1) * GBK);
                stB[p] = *(const float4*)(Bg[p] + (kb + 1) * GBK);
            }
        }
        const float* Abuf = sm + cur * 4096;
        const float* Bbuf = sm + 8192 + cur * 4096;

        Frag8 fa[2][2];
        #pragma unroll
        for (int mt = 0; mt < 2; mt++)
            #pragma unroll
            for (int rr = 0; rr < 2; rr++) {
                int r = wm * 32 + mt * 16 + rr * 8 + g;
                const float* base = Abuf + r * 32;
                #pragma unroll
                for (int u = 0; u < 2; u++) {
                    int f4p = (2 * c + u) ^ (r & 7);
                    *(float4*)&fa[mt][rr].v[4 * u] = *(const float4*)(base + f4p * 4);
                }
            }
        Frag8 fb[8];
        #pragma unroll
        for (int nt = 0; nt < 8; nt++) {
            int r = wn * 64 + nt * 8 + g;
            const float* base = Bbuf + r * 32;
            #pragma unroll
            for (int u = 0; u < 2; u++) {
                int f4p = (2 * c + u) ^ (r & 7);
                *(float4*)&fb[nt].v[4 * u] = *(const float4*)(base + f4p * 4);
            }
        }

        #pragma unroll
        for (int s = 0; s < 4; s++)
            #pragma unroll
            for (int mt = 0; mt < 2; mt++)
                #pragma unroll
                for (int nt = 0; nt < 8; nt++)
                    mma_tf32(acc[mt][nt],
                        fa[mt][0].v[2*s], fa[mt][1].v[2*s],
                        fa[mt][0].v[2*s+1], fa[mt][1].v[2*s+1],
                        fb[nt].v[2*s], fb[nt].v[2*s+1]);

        if (kb + 1 < kt) {
            int nxt = 1 - cur;
            stage_tile(stA, sm + nxt * 4096, tid);
            stage_tile(stB, sm + 8192 + nxt * 4096, tid);
        }
        __syncthreads();
    }

    int row0g = bm * GBM + wm * 32;
    int col0g = bn * GBN + wn * 64;
    #pragma unroll
    for (int mt = 0; mt < 2; mt++)
        #pragma unroll
        for (int nt = 0; nt < 8; nt++)
            #pragma unroll
            for (int h2 = 0; h2 < 2; h2++) {
                int row = row0g + mt * 16 + h2 * 8 + g;
                int col = col0g + nt * 8 + 2 * c;
                float2 v;
                v.x = acc[mt][nt][2 * h2 + 0] + bias[col];
                v.y = acc[mt][nt][2 * h2 + 1] + bias[col + 1];
                size_t off = (size_t)row * N + col;
                if (EPI == 1) {
                    float2 r = *(const float2*)(res + off);
                    v.x += r.x; v.y += r.y;
                }
                if (EPI == 2) {
                    v.x = gelu_exact(v.x); v.y = gelu_exact(v.y);
                }
                *(float2*)(C + off) = v;
            }
}

// ============================ tf32 tensor-core flash attention ============================
// CTA: 128 queries x 64-key tiles, 8 warps (16 q-rows each), 256 threads.
// smem (plain row-major, strides chosen for conflict-free scalar fragment reads):
//   Qs [128][132]  (132 % 32 == 4: bank = 4g + c, conflict-free)
//   Ks [ 64][132]
//   Vs [ 64][136]  (136 % 32 == 8: bank = 8c + g, conflict-free)
//   Ps [128][ 68]  ( 68 % 32 == 4)
#define SQ_STR 132
#define SK_STR 132
#define SV_STR 136
#define SP_STR 68
#define ATT_SMEM ((128*SQ_STR + 64*SK_STR + 64*SV_STR + 128*SP_STR) * 4)
#define NEG_BIG (-1e30f)

__global__ void __launch_bounds__(256, 1) attn_kernel(
    const float* __restrict__ qkv, const float* __restrict__ slopes,
    float* __restrict__ out)
{
    extern __shared__ float sm[];
    float* Qs = sm;                          // [128][SQ_STR]
    float* Ks = Qs + 128 * SQ_STR;           // [64][SK_STR]
    float* Vs = Ks + 64 * SK_STR;            // [64][SV_STR]
    float* Ps = Vs + 64 * SV_STR;            // [128][SP_STR]

    int qi = blockIdx.x, h = blockIdx.y, b = blockIdx.z;
    int tid = threadIdx.x, warp = tid >> 5, lane = tid & 31;
    int g = lane >> 2, c = lane & 3;
    int q0 = qi * 128;
    float slope = slopes[h];
    const float scale = 0.08838834764831845f;   // 1/sqrt(128)

    const float* qbase = qkv + (size_t)(b * SEQ) * QKV_N + h * HD;
    const float* kbase = qbase + D_MODEL;
    const float* vbase = qbase + 2 * D_MODEL;

    // stage Q (scaled + tf32-rounded), resident for whole CTA
    for (int i = tid; i < 128 * 32; i += 256) {
        int r = i >> 5, f4 = i & 31;
        float4 v = *(const float4*)(qbase + (size_t)(q0 + r) * QKV_N + f4 * 4);
        float* d = &Qs[r * SQ_STR + f4 * 4];
        d[0] = tf32r(v.x * scale); d[1] = tf32r(v.y * scale);
        d[2] = tf32r(v.z * scale); d[3] = tf32r(v.w * scale);
    }

    float m0 = NEG_BIG, m1 = NEG_BIG, l0 = 0.f, l1 = 0.f;
    float oc[16][4];
    #pragma unroll
    for (int nt = 0; nt < 16; nt++)
        #pragma unroll
        for (int q = 0; q < 4; q++) oc[nt][q] = 0.f;

    int rowA = 16 * warp + g;        // tile-local row for c0/c1 (rowA+8 for c2/c3)
    int qr0 = q0 + rowA, qr1 = qr0 + 8;
    const float* qa0 = &Qs[rowA * SQ_STR];
    const float* qa1 = qa0 + 8 * SQ_STR;
    float* pw0 = &Ps[rowA * SP_STR];
    float* pw1 = pw0 + 8 * SP_STR;

    int ntiles = 2 * qi + 2;
    for (int jt = 0; jt < ntiles; jt++) {
        int j0 = jt * 64;
        __syncthreads();  // prior tile's reads of Ks/Vs complete
        // stage K, V (tf32-rounded)
        for (int i = tid; i < 64 * 32; i += 256) {
            int r = i >> 5, f4 = i & 31;
            float4 kv = *(const float4*)(kbase + (size_t)(j0 + r) * QKV_N + f4 * 4);
            float* kd = &Ks[r * SK_STR + f4 * 4];
            kd[0] = tf32r(kv.x); kd[1] = tf32r(kv.y);
            kd[2] = tf32r(kv.z); kd[3] = tf32r(kv.w);
            float4 vv = *(const float4*)(vbase + (size_t)(j0 + r) * QKV_N + f4 * 4);
            float* vd = &Vs[r * SV_STR + f4 * 4];
            vd[0] = tf32r(vv.x); vd[1] = tf32r(vv.y);
            vd[2] = tf32r(vv.z); vd[3] = tf32r(vv.w);
        }
        __syncthreads();

        // ---- S = Q K^T ----
        float sc[8][4];
        #pragma unroll
        for (int nt = 0; nt < 8; nt++)
            #pragma unroll
            for (int q = 0; q < 4; q++) sc[nt][q] = 0.f;

        #pragma unroll 4
        for (int s = 0; s < 16; s++) {
            int k0 = 8 * s;
            float a0 = qa0[k0 + c];
            float a1 = qa1[k0 + c];
            float a2 = qa0[k0 + c + 4];
            float a3 = qa1[k0 + c + 4];
            #pragma unroll
            for (int nt = 0; nt < 8; nt++) {
                const float* kr = &Ks[(nt * 8 + g) * SK_STR + k0];
                mma_tf32(sc[nt], a0, a1, a2, a3, kr[c], kr[c + 4]);
            }
        }

        // ---- ALiBi + causal mask + online softmax ----
        bool masked = (jt >= 2 * qi);
        float tm0 = NEG_BIG, tm1 = NEG_BIG;
        #pragma unroll
        for (int nt = 0; nt < 8; nt++) {
            #pragma unroll
            for (int j = 0; j < 2; j++) {
                int col = j0 + nt * 8 + 2 * c + j;
                float d0 = (float)(col - qr0);
                float d1 = (float)(col - qr1);
                float s0 = sc[nt][j]     + slope * d0;
                float s1 = sc[nt][2 + j] + slope * d1;
                if (masked) {
                    if (col > qr0) s0 = NEG_BIG;
                    if (col > qr1) s1 = NEG_BIG;
                }
                sc[nt][j] = s0; sc[nt][2 + j] = s1;
                tm0 = fmaxf(tm0, s0); tm1 = fmaxf(tm1, s1);
            }
        }
        #pragma unroll
        for (int o = 1; o < 4; o <<= 1) {
            tm0 = fmaxf(tm0, __shfl_xor_sync(0xffffffffu, tm0, o));
            tm1 = fmaxf(tm1, __shfl_xor_sync(0xffffffffu, tm1, o));
        }
        float mn0 = fmaxf(m0, tm0), mn1 = fmaxf(m1, tm1);
        float alpha0 = __expf(m0 - mn0), alpha1 = __expf(m1 - mn1);
        float rs0 = 0.f, rs1 = 0.f;
        #pragma unroll
        for (int nt = 0; nt < 8; nt++) {
            #pragma unroll
            for (int j = 0; j < 2; j++) {
                float p0 = __expf(sc[nt][j]     - mn0);
                float p1 = __expf(sc[nt][2 + j] - mn1);
                sc[nt][j] = p0; sc[nt][2 + j] = p1;
                rs0 += p0; rs1 += p1;
            }
        }
        #pragma unroll
        for (int o = 1; o < 4; o <<= 1) {
            rs0 += __shfl_xor_sync(0xffffffffu, rs0, o);
            rs1 += __shfl_xor_sync(0xffffffffu, rs1, o);
        }
        l0 = l0 * alpha0 + rs0;
        l1 = l1 * alpha1 + rs1;
        m0 = mn0; m1 = mn1;
        #pragma unroll
        for (int nt = 0; nt < 16; nt++) {
            oc[nt][0] *= alpha0; oc[nt][1] *= alpha0;
            oc[nt][2] *= alpha1; oc[nt][3] *= alpha1;
        }

        // ---- stage P (tf32-rounded); same warp reads it back ----
        #pragma unroll
        for (int nt = 0; nt < 8; nt++) {
            float2 w0 = make_float2(tf32r(sc[nt][0]), tf32r(sc[nt][1]));
            float2 w1 = make_float2(tf32r(sc[nt][2]), tf32r(sc[nt][3]));
            *(float2*)&pw0[nt * 8 + 2 * c] = w0;
            *(float2*)&pw1[nt * 8 + 2 * c] = w1;
        }
        __syncwarp();

        // ---- O += P @ V ----
        #pragma unroll 2
        for (int s = 0; s < 8; s++) {
            int k0 = 8 * s;
            float a0 = pw0[k0 + c];
            float a1 = pw1[k0 + c];
            float a2 = pw0[k0 + c + 4];
            float a3 = pw1[k0 + c + 4];
            const float* v0r = &Vs[(k0 + c) * SV_STR + g];
            const float* v1r = &Vs[(k0 + c + 4) * SV_STR + g];
            #pragma unroll
            for (int nt = 0; nt < 16; nt++)
                mma_tf32(oc[nt], a0, a1, a2, a3, v0r[nt * 8], v1r[nt * 8]);
        }
    }

    // ---- normalize + write out ----
    float inv0 = 1.f / l0, inv1 = 1.f / l1;
    float* ob = out + (size_t)(b * SEQ + qr0) * D_MODEL + h * HD;
    float* ob1 = ob + 8 * D_MODEL;
    #pragma unroll
    for (int nt = 0; nt < 16; nt++) {
        *(float2*)&ob[nt * 8 + 2 * c]  = make_float2(oc[nt][0] * inv0, oc[nt][1] * inv0);
        *(float2*)&ob1[nt * 8 + 2 * c] = make_float2(oc[nt][2] * inv1, oc[nt][3] * inv1);
    }
}

// ============================ launch ============================
extern "C" void kernel_launch(void* const* d_in, const int* in_sizes, int n_in,
                              void* d_out, int out_size)
{
    const float* x      = (const float*)d_in[0];
    const float* ln1_w  = (const float*)d_in[1];
    const float* ln1_b  = (const float*)d_in[2];
    const float* Wqkv   = (const float*)d_in[3];
    const float* bqkv   = (const float*)d_in[4];
    const float* Wo     = (const float*)d_in[5];
    const float* bo     = (const float*)d_in[6];
    const float* ln2_w  = (const float*)d_in[7];
    const float* ln2_b  = (const float*)d_in[8];
    const float* W1     = (const float*)d_in[9];
    const float* b1     = (const float*)d_in[10];
    const float* W2     = (const float*)d_in[11];
    const float* b2     = (const float*)d_in[12];
    const float* slopes = (const float*)d_in[13];
    float* out = (float*)d_out;

    float *h, *qkv, *attn, *mlp;
    cudaGetSymbolAddress((void**)&h,    g_h);
    cudaGetSymbolAddress((void**)&qkv,  g_qkv);
    cudaGetSymbolAddress((void**)&attn, g_attn);
    cudaGetSymbolAddress((void**)&mlp,  g_mlp);

    cudaFuncSetAttribute(attn_kernel,
                         cudaFuncAttributeMaxDynamicSharedMemorySize, ATT_SMEM);
    cudaFuncSetAttribute(gemm_kernel<0>,
                         cudaFuncAttributeMaxDynamicSharedMemorySize, GEMM_SMEM);
    cudaFuncSetAttribute(gemm_kernel<1>,
                         cudaFuncAttributeMaxDynamicSharedMemorySize, GEMM_SMEM);
    cudaFuncSetAttribute(gemm_kernel<2>,
                         cudaFuncAttributeMaxDynamicSharedMemorySize, GEMM_SMEM);

    // 1. LN1
    ln_kernel<<<ROWS, 256>>>(x, ln1_w, ln1_b, h);
    // 2. QKV GEMM
    gemm_kernel<0><<<dim3(QKV_N / GBN, ROWS / GBM), 256, GEMM_SMEM>>>(
        h, Wqkv, bqkv, nullptr, qkv, ROWS, QKV_N, D_MODEL);
    // 3. Flash attention with ALiBi (tensor cores)
    attn_kernel<<<dim3(SEQ / 128, NH, BATCH), 256, ATT_SMEM>>>(qkv, slopes, attn);
    // 4. O projection + residual (x)  -> d_out holds x1
    gemm_kernel<1><<<dim3(D_MODEL / GBN, ROWS / GBM), 256, GEMM_SMEM>>>(
        attn, Wo, bo, x, out, ROWS, D_MODEL, D_MODEL);
    // 5. LN2
    ln_kernel<<<ROWS, 256>>>(out, ln2_w, ln2_b, h);
    // 6. MLP up + GELU
    gemm_kernel<2><<<dim3(D_FF / GBN, ROWS / GBM), 256, GEMM_SMEM>>>(
        h, W1, b1, nullptr, mlp, ROWS, D_FF, D_MODEL);
    // 7. MLP down + residual (x1 in d_out) -> d_out final
    gemm_kernel<1><<<dim3(D_MODEL / GBN, ROWS / GBM), 256, GEMM_SMEM>>>(
        mlp, W2, b2, out, out, ROWS, D_MODEL, D_FF);
}